// round 1
// baseline (speedup 1.0000x reference)
#include <cuda_runtime.h>

// Problem constants (fixed by the dataset)
#define NPIX 147456        // 384*384
#define NNZC 1474560       // NPIX/2 * 20
#define NLOC 73728         // NPIX/2
#define KIU  5
#define TPB  256
#define CG_STEPS 30

// ---------------- device scratch (static allocation only) ----------------
__device__ float g_cm_vals[NNZC];
__device__ float g_rs_cm[NPIX];
__device__ float g_D[NPIX];            // rs_m + rs_c + diag_ku
__device__ float g_Smat[81 * NLOC];    // layout [(i*9+j)*NLOC + k]
__device__ float g_Wiu[KIU * NLOC];    // layout [l*NLOC + k]
__device__ float g_r[NPIX];
__device__ float g_p[NPIX];
__device__ float g_Ap[NPIX];
__device__ float g_Lv[NPIX];
__device__ float g_Scm[NPIX];
__device__ double g_scal[3];           // [0]=rs_cur  [1]=pAp  [2]=rs_new

// ---------------- helpers ----------------
__device__ __forceinline__ double blockReduceD(double v) {
    __shared__ double sm[32];
    int lane = threadIdx.x & 31;
    int wid  = threadIdx.x >> 5;
    #pragma unroll
    for (int o = 16; o > 0; o >>= 1) v += __shfl_down_sync(0xffffffffu, v, o);
    if (lane == 0) sm[wid] = v;
    __syncthreads();
    v = (threadIdx.x < (blockDim.x >> 5)) ? sm[lane] : 0.0;
    if (wid == 0) {
        #pragma unroll
        for (int o = 16; o > 0; o >>= 1) v += __shfl_down_sync(0xffffffffu, v, o);
    }
    return v; // valid on thread 0
}

__device__ __forceinline__ int off9(int i, int W) {
    // offs = {-1-W, -1, -1+W, -W, 0, W, 1-W, 1, 1+W}
    int a = i / 3;        // 0,1,2 -> column group
    int b = i % 3;        // 0,1,2 -> row group
    return (a - 1) + (b - 1) * W;
}

// ---------------- setup kernels ----------------
__global__ void k_p0() {
    int i = blockIdx.x * blockDim.x + threadIdx.x;
    if (i < NPIX) { g_rs_cm[i] = 0.f; g_D[i] = 0.f; g_Scm[i] = 0.f; }
    if (i < 3) g_scal[i] = 0.0;
}

__global__ void k_p1(const float* __restrict__ CMw, const float* __restrict__ Wd,
                     const int* __restrict__ row) {
    int k = blockIdx.x * blockDim.x + threadIdx.x;
    if (k >= NNZC) return;
    int r = row[k];
    float cv = CMw[r] * Wd[k];
    g_cm_vals[k] = cv;
    atomicAdd(&g_rs_cm[r], cv);
}

__global__ void k_p2(const float* __restrict__ LOCw, const float* __restrict__ LF,
                     const int* __restrict__ inInd, const int* __restrict__ widthp) {
    int tid = blockIdx.x * blockDim.x + threadIdx.x;
    if (tid >= 9 * NLOC) return;
    int W = widthp ? widthp[0] : 384;
    int i = tid / NLOC;
    int k = tid - i * NLOC;
    int ind = inInd[k];
    float w = LOCw[ind];
    float rowsum = 0.f;
    #pragma unroll
    for (int j = 0; j < 9; j++) {
        float s = 0.5f * w * (LF[(j * 9 + i) * NLOC + k] + LF[(i * 9 + j) * NLOC + k]);
        g_Smat[(i * 9 + j) * NLOC + k] = s;
        rowsum += s;
    }
    atomicAdd(&g_D[ind + off9(i, W)], rowsum);
}

__global__ void k_p3(const float* __restrict__ IUw, const float* __restrict__ IUf,
                     const int* __restrict__ inInd, const int* __restrict__ nbInd) {
    int k = blockIdx.x * blockDim.x + threadIdx.x;
    if (k >= NLOC) return;
    int ind = inInd[k];
    float w = IUw[ind];
    #pragma unroll
    for (int l = 0; l < KIU; l++) {
        float wv = 0.5f * w * IUf[k * KIU + l];
        g_Wiu[l * NLOC + k] = wv;
        atomicAdd(&g_D[ind], wv);
        atomicAdd(&g_D[nbInd[k * KIU + l]], wv);
    }
}

__global__ void k_p4(const float* __restrict__ KUw, const float* __restrict__ kToUconf,
                     const float* __restrict__ known, const float* __restrict__ kToU,
                     const float* __restrict__ lmbda, float* __restrict__ x) {
    int i = blockIdx.x * blockDim.x + threadIdx.x;
    double c = 0.0;
    if (i < NPIX) {
        float dk = KUw[i] * kToUconf[i] + lmbda[0] * known[i];
        float b  = dk * kToU[i];
        g_D[i] += dk;
        g_r[i] = b;
        g_p[i] = b;
        x[i] = 0.f;
        c = (double)b * (double)b;
    }
    double s = blockReduceD(c);
    if (threadIdx.x == 0) atomicAdd(&g_scal[0], s);
}

// ---------------- per-iteration kernels ----------------
// S1: Scm[row] += cm_val * p[col]; also scalar shuffle for iterations > 0
__global__ void k_s1(const int* __restrict__ row, const int* __restrict__ col, int doSwap) {
    int k = blockIdx.x * blockDim.x + threadIdx.x;
    if (k == 0 && doSwap) {
        g_scal[0] = g_scal[2];
        g_scal[1] = 0.0;
        g_scal[2] = 0.0;
    }
    if (k >= NNZC) return;
    atomicAdd(&g_Scm[row[k]], g_cm_vals[k] * g_p[col[k]]);
}

// LV: Lv = rs_cm*p - Scm;  Ap_init = rs_cm*Lv + D*p;  pAp += p*Ap_init
__global__ void k_lv() {
    int i = blockIdx.x * blockDim.x + threadIdx.x;
    double c = 0.0;
    if (i < NPIX) {
        float pi = g_p[i];
        float rc = g_rs_cm[i];
        float lv = rc * pi - g_Scm[i];
        g_Lv[i] = lv;
        float ap = rc * lv + g_D[i] * pi;
        g_Ap[i] = ap;
        c = (double)pi * (double)ap;
    }
    double s = blockReduceD(c);
    if (threadIdx.x == 0) atomicAdd(&g_scal[1], s);
}

// SC2: all off-diagonal scatters into Ap + fused pAp contributions
__global__ void k_sc2(const int* __restrict__ row, const int* __restrict__ col,
                      const int* __restrict__ locInd, const int* __restrict__ iuInd,
                      const int* __restrict__ iuNb, const int* __restrict__ widthp) {
    int tid = blockIdx.x * blockDim.x + threadIdx.x;
    double c = 0.0;
    if (tid < NNZC) {
        int rr = row[tid], cc = col[tid];
        float add = -g_cm_vals[tid] * g_Lv[rr];
        atomicAdd(&g_Ap[cc], add);
        c = (double)add * (double)g_p[cc];
    } else if (tid < NNZC + 9 * NLOC) {
        int t = tid - NNZC;
        int i = t / NLOC;
        int k = t - i * NLOC;
        int W = widthp ? widthp[0] : 384;
        int ind = locInd[k];
        float acc = 0.f;
        #pragma unroll
        for (int j = 0; j < 9; j++)
            acc += g_Smat[(i * 9 + j) * NLOC + k] * g_p[ind + off9(j, W)];
        int tgt = ind + off9(i, W);
        atomicAdd(&g_Ap[tgt], -acc);
        c = (double)(-acc) * (double)g_p[tgt];
    } else if (tid < NNZC + 9 * NLOC + NLOC) {
        int k = tid - NNZC - 9 * NLOC;
        int ind = iuInd[k];
        float pind = g_p[ind];
        float acc = 0.f;
        #pragma unroll
        for (int l = 0; l < KIU; l++) {
            float w = g_Wiu[l * NLOC + k];
            int nb = iuNb[k * KIU + l];
            float pnb = g_p[nb];
            acc += w * pnb;
            float add = -w * pind;
            atomicAdd(&g_Ap[nb], add);
            c += (double)add * (double)pnb;
        }
        atomicAdd(&g_Ap[ind], -acc);
        c += (double)(-acc) * (double)pind;
    }
    double s = blockReduceD(c);
    if (threadIdx.x == 0) atomicAdd(&g_scal[1], s);
}

// UPD1: alpha = rs/pAp; x += a*p; r -= a*Ap; rs_new += r*r
__global__ void k_upd1(float* __restrict__ x) {
    int i = blockIdx.x * blockDim.x + threadIdx.x;
    double c = 0.0;
    if (i < NPIX) {
        float alpha = (float)(g_scal[0] / g_scal[1]);
        x[i] += alpha * g_p[i];
        float rn = g_r[i] - alpha * g_Ap[i];
        g_r[i] = rn;
        c = (double)rn * (double)rn;
    }
    double s = blockReduceD(c);
    if (threadIdx.x == 0) atomicAdd(&g_scal[2], s);
}

// UPD2: p = r + beta*p; zero Scm for next iteration
__global__ void k_upd2() {
    int i = blockIdx.x * blockDim.x + threadIdx.x;
    if (i >= NPIX) return;
    float beta = (float)(g_scal[2] / g_scal[0]);
    g_p[i] = g_r[i] + beta * g_p[i];
    g_Scm[i] = 0.f;
}

// ---------------- host launch ----------------
extern "C" void kernel_launch(void* const* d_in, const int* in_sizes, int n_in,
                              void* d_out, int out_size) {
    const float* CMw    = (const float*)d_in[0];
    const float* LOCw   = (const float*)d_in[1];
    const float* IUw    = (const float*)d_in[2];
    const float* KUw    = (const float*)d_in[3];
    const float* lmbda  = (const float*)d_in[4];
    const float* kToUcf = (const float*)d_in[5];
    const float* known  = (const float*)d_in[6];
    const float* kToU   = (const float*)d_in[7];
    const float* Wd     = (const float*)d_in[8];
    const float* LF     = (const float*)d_in[9];
    const float* IUf    = (const float*)d_in[10];
    const int*   wrow   = (const int*)d_in[11];
    const int*   wcol   = (const int*)d_in[12];
    const int*   locInd = (const int*)d_in[13];
    const int*   iuInd  = (const int*)d_in[14];
    const int*   iuNb   = (const int*)d_in[15];
    const int*   widthp = (n_in > 16) ? (const int*)d_in[16] : nullptr;
    float* x = (float*)d_out;

    const int gN   = (NPIX + TPB - 1) / TPB;
    const int gNNZ = (NNZC + TPB - 1) / TPB;
    const int gP2  = (9 * NLOC + TPB - 1) / TPB;
    const int gL   = (NLOC + TPB - 1) / TPB;
    const int totSC2 = NNZC + 9 * NLOC + NLOC;
    const int gSC2 = (totSC2 + TPB - 1) / TPB;

    k_p0<<<gN, TPB>>>();
    k_p1<<<gNNZ, TPB>>>(CMw, Wd, wrow);
    k_p2<<<gP2, TPB>>>(LOCw, LF, locInd, widthp);
    k_p3<<<gL, TPB>>>(IUw, IUf, iuInd, iuNb);
    k_p4<<<gN, TPB>>>(KUw, kToUcf, known, kToU, lmbda, x);

    for (int it = 0; it < CG_STEPS; it++) {
        k_s1<<<gNNZ, TPB>>>(wrow, wcol, it > 0 ? 1 : 0);
        k_lv<<<gN, TPB>>>();
        k_sc2<<<gSC2, TPB>>>(wrow, wcol, locInd, iuInd, iuNb, widthp);
        k_upd1<<<gN, TPB>>>(x);
        k_upd2<<<gN, TPB>>>();
    }
}

// round 2
// speedup vs baseline: 1.3720x; 1.3720x over previous
#include <cuda_runtime.h>

// ---------------- problem constants (fixed by dataset) ----------------
#define NPIX 147456        // 384*384
#define W384 384
#define NNZC 1474560       // NPIX/2 * 20
#define NLOC 73728         // NPIX/2
#define KIU  5
#define CG_STEPS 30

#define TPB   256
#define NBLK  592          // 148 SMs * 4 blocks (GB300 has 152 SMs -> all resident)

// ---------------- device scratch (static only) ----------------
__device__ float g_cm_vals[NNZC];      // original-order cm values
__device__ float g_vals_s[NNZC];       // CSR-sorted (by row) values
__device__ int   g_col_s[NNZC];        // CSR-sorted cols
__device__ float g_vals_c[NNZC];       // CSC-sorted (by col) values
__device__ int   g_row_c[NNZC];        // CSC-sorted rows
__device__ int   g_ptrR[NPIX + 1];
__device__ int   g_ptrC[NPIX + 1];
__device__ int   g_cntR[NPIX];
__device__ int   g_cntC[NPIX];
__device__ int   g_tmpR[NPIX];
__device__ int   g_tmpC[NPIX];
__device__ int   g_btot[288];
__device__ int   g_boff[288];

__device__ float g_rs_cm[NPIX];
__device__ float g_D[NPIX];            // rs_m + rs_c + diag_ku
__device__ float g_Smat[81 * NLOC];    // [(i*9+j)*NLOC + k]
__device__ float g_Wiu[KIU * NLOC];    // [l*NLOC + k]
__device__ float g_r[NPIX];
__device__ float g_p[NPIX];
__device__ float g_Ap[NPIX];
__device__ float g_Lv[NPIX];
__device__ double g_scal[3];
__device__ double g_dotA[NBLK];
__device__ double g_dotC[NBLK];
__device__ double g_rsn[NBLK];

__device__ unsigned g_count;
__device__ volatile unsigned g_sense;

// ---------------- helpers ----------------
__device__ __forceinline__ int OFF9(int i) {
    int a = i / 3, b = i % 3;
    return (a - 1) + (b - 1) * W384;
}

__device__ __forceinline__ double bred(double v, double* sm) {
    int lane = threadIdx.x & 31, w = threadIdx.x >> 5;
    #pragma unroll
    for (int o = 16; o > 0; o >>= 1) v += __shfl_down_sync(0xffffffffu, v, o);
    if (lane == 0) sm[w] = v;
    __syncthreads();
    if (w == 0) {
        v = (lane < (TPB >> 5)) ? sm[lane] : 0.0;
        #pragma unroll
        for (int o = 4; o > 0; o >>= 1) v += __shfl_down_sync(0xffu, v, o);
    }
    __syncthreads();
    return v; // valid on thread 0
}

__device__ __forceinline__ void gbar(unsigned &ep) {
    ep++;
    __syncthreads();
    if (threadIdx.x == 0) {
        __threadfence();
        if (atomicAdd(&g_count, 1u) == NBLK - 1) {
            g_count = 0;
            __threadfence();
            g_sense = ep;
        } else {
            while (g_sense != ep) { __nanosleep(64); }
            __threadfence();
        }
    }
    __syncthreads();
}

// ---------------- setup kernels ----------------
__global__ void k_z() {
    int i = blockIdx.x * blockDim.x + threadIdx.x;
    if (i < NPIX) {
        g_cntR[i] = 0; g_cntC[i] = 0; g_tmpR[i] = 0; g_tmpC[i] = 0;
        g_rs_cm[i] = 0.f; g_D[i] = 0.f;
    }
    if (i < 3) g_scal[i] = 0.0;
    if (i == 0) { g_count = 0; g_sense = 0; }
}

__global__ void k_cnt(const float* __restrict__ CMw, const float* __restrict__ Wd,
                      const int* __restrict__ row, const int* __restrict__ col) {
    int k = blockIdx.x * blockDim.x + threadIdx.x;
    if (k >= NNZC) return;
    int r = row[k], c = col[k];
    float cv = CMw[r] * Wd[k];
    g_cm_vals[k] = cv;
    atomicAdd(&g_rs_cm[r], cv);
    atomicAdd(&g_cntR[r], 1);
    atomicAdd(&g_cntC[c], 1);
}

// 288 blocks x 1024: blocks 0..143 scan cntR, 144..287 scan cntC (within-block)
__global__ void k_scanA() {
    __shared__ int sm[1024];
    int half = blockIdx.x / 144;
    int blk  = blockIdx.x % 144;
    int gi   = blk * 1024 + threadIdx.x;
    int* cnt = half ? g_cntC : g_cntR;
    int* ptr = half ? g_ptrC : g_ptrR;
    int v = cnt[gi];
    sm[threadIdx.x] = v;
    __syncthreads();
    for (int o = 1; o < 1024; o <<= 1) {
        int t = (threadIdx.x >= o) ? sm[threadIdx.x - o] : 0;
        __syncthreads();
        sm[threadIdx.x] += t;
        __syncthreads();
    }
    ptr[gi] = sm[threadIdx.x] - v;           // within-block exclusive
    if (threadIdx.x == 1023) g_btot[blockIdx.x] = sm[1023];
}

__global__ void k_scanB() {
    if (threadIdx.x == 0) {
        int acc = 0;
        for (int i = 0; i < 144; i++) { g_boff[i] = acc; acc += g_btot[i]; }
        acc = 0;
        for (int i = 144; i < 288; i++) { g_boff[i] = acc; acc += g_btot[i]; }
    }
}

__global__ void k_scanC() {
    int half = blockIdx.x / 144;
    int blk  = blockIdx.x % 144;
    int gi   = blk * 1024 + threadIdx.x;
    int* ptr = half ? g_ptrC : g_ptrR;
    ptr[gi] += g_boff[blockIdx.x];
    if (blockIdx.x == 0 && threadIdx.x == 0) {
        g_ptrR[NPIX] = NNZC;
        g_ptrC[NPIX] = NNZC;
    }
}

__global__ void k_scatter(const int* __restrict__ row, const int* __restrict__ col) {
    int k = blockIdx.x * blockDim.x + threadIdx.x;
    if (k >= NNZC) return;
    int r = row[k], c = col[k];
    float cv = g_cm_vals[k];
    int p1 = g_ptrR[r] + atomicAdd(&g_tmpR[r], 1);
    g_vals_s[p1] = cv; g_col_s[p1] = c;
    int p2 = g_ptrC[c] + atomicAdd(&g_tmpC[c], 1);
    g_vals_c[p2] = cv; g_row_c[p2] = r;
}

__global__ void k_p2(const float* __restrict__ LOCw, const float* __restrict__ LF,
                     const int* __restrict__ inInd) {
    int tid = blockIdx.x * blockDim.x + threadIdx.x;
    if (tid >= 9 * NLOC) return;
    int i = tid / NLOC;
    int k = tid - i * NLOC;
    int ind = inInd[k];
    float w = LOCw[ind];
    float rowsum = 0.f;
    #pragma unroll
    for (int j = 0; j < 9; j++) {
        float s = 0.5f * w * (LF[(j * 9 + i) * NLOC + k] + LF[(i * 9 + j) * NLOC + k]);
        g_Smat[(i * 9 + j) * NLOC + k] = s;
        rowsum += s;
    }
    atomicAdd(&g_D[ind + OFF9(i)], rowsum);
}

__global__ void k_p3(const float* __restrict__ IUw, const float* __restrict__ IUf,
                     const int* __restrict__ inInd, const int* __restrict__ nbInd) {
    int k = blockIdx.x * blockDim.x + threadIdx.x;
    if (k >= NLOC) return;
    int ind = inInd[k];
    float w = IUw[ind];
    #pragma unroll
    for (int l = 0; l < KIU; l++) {
        float wv = 0.5f * w * IUf[k * KIU + l];
        g_Wiu[l * NLOC + k] = wv;
        atomicAdd(&g_D[ind], wv);
        atomicAdd(&g_D[nbInd[k * KIU + l]], wv);
    }
}

__global__ void k_p4(const float* __restrict__ KUw, const float* __restrict__ kToUconf,
                     const float* __restrict__ known, const float* __restrict__ kToU,
                     const float* __restrict__ lmbda, float* __restrict__ x) {
    __shared__ double sm[8];
    int i = blockIdx.x * blockDim.x + threadIdx.x;
    double c = 0.0;
    if (i < NPIX) {
        float dk = KUw[i] * kToUconf[i] + lmbda[0] * known[i];
        float b  = dk * kToU[i];
        g_D[i] += dk;
        g_r[i] = b;
        g_p[i] = b;
        x[i] = 0.f;
        c = (double)b * (double)b;
    }
    c = bred(c, sm);
    if (threadIdx.x == 0) atomicAdd(&g_scal[0], c);
}

// ---------------- persistent CG kernel ----------------
__global__ void __launch_bounds__(TPB, 4) k_cg(
    float* __restrict__ x,
    const int* __restrict__ locInd,
    const int* __restrict__ iuInd,
    const int* __restrict__ iuNb)
{
    __shared__ double sred[8];
    __shared__ double s_rs, s_alpha, s_beta;
    const int tid  = threadIdx.x;
    const int gtid = blockIdx.x * TPB + tid;
    unsigned ep = 0;

    if (tid == 0) s_rs = g_scal[0];
    __syncthreads();

    for (int it = 0; it < CG_STEPS; ++it) {
        // ---- Phase A: Scm (CSR gather) -> Lv -> Ap_init -> diag dot
        double dA = 0.0;
        if (gtid < NPIX) {
            int b0 = g_ptrR[gtid], b1 = g_ptrR[gtid + 1];
            float acc = 0.f;
            int k = b0;
            for (; k + 4 <= b1; k += 4) {
                float v0 = g_vals_s[k],     v1 = g_vals_s[k + 1];
                float v2 = g_vals_s[k + 2], v3 = g_vals_s[k + 3];
                int  c0 = g_col_s[k],     c1 = g_col_s[k + 1];
                int  c2 = g_col_s[k + 2], c3 = g_col_s[k + 3];
                acc += v0 * g_p[c0] + v1 * g_p[c1] + v2 * g_p[c2] + v3 * g_p[c3];
            }
            for (; k < b1; k++) acc += g_vals_s[k] * g_p[g_col_s[k]];
            float pi = g_p[gtid], rc = g_rs_cm[gtid];
            float lv = rc * pi - acc;
            g_Lv[gtid] = lv;
            float ap = rc * lv + g_D[gtid] * pi;
            g_Ap[gtid] = ap;
            dA = (double)pi * (double)ap;
        }
        dA = bred(dA, sred);
        if (tid == 0) g_dotA[blockIdx.x] = dA;
        gbar(ep);

        // ---- Phase C: all off-diagonal scatters + fused dot contributions
        double dC = 0.0;
        if (gtid < NPIX) {
            int b0 = g_ptrC[gtid], b1 = g_ptrC[gtid + 1];
            float acc = 0.f;
            int k = b0;
            for (; k + 4 <= b1; k += 4) {
                float v0 = g_vals_c[k],     v1 = g_vals_c[k + 1];
                float v2 = g_vals_c[k + 2], v3 = g_vals_c[k + 3];
                int  r0 = g_row_c[k],     r1 = g_row_c[k + 1];
                int  r2 = g_row_c[k + 2], r3 = g_row_c[k + 3];
                acc += v0 * g_Lv[r0] + v1 * g_Lv[r1] + v2 * g_Lv[r2] + v3 * g_Lv[r3];
            }
            for (; k < b1; k++) acc += g_vals_c[k] * g_Lv[g_row_c[k]];
            atomicAdd(&g_Ap[gtid], -acc);
            dC = -(double)acc * (double)g_p[gtid];
        }
        if (gtid < NLOC) {
            // matting 9x9 block
            int ind = locInd[gtid];
            float pn[9];
            #pragma unroll
            for (int i = 0; i < 9; i++) pn[i] = g_p[ind + OFF9(i)];
            #pragma unroll
            for (int i = 0; i < 9; i++) {
                float acc = 0.f;
                #pragma unroll
                for (int j = 0; j < 9; j++)
                    acc += g_Smat[(i * 9 + j) * NLOC + gtid] * pn[j];
                atomicAdd(&g_Ap[ind + OFF9(i)], -acc);
                dC -= (double)acc * (double)pn[i];
            }
            // IU KNN
            int ind2 = iuInd[gtid];
            float pind = g_p[ind2];
            float acc2 = 0.f;
            #pragma unroll
            for (int l = 0; l < KIU; l++) {
                float w = g_Wiu[l * NLOC + gtid];
                int nb  = iuNb[gtid * KIU + l];
                float pnb = g_p[nb];
                acc2 += w * pnb;
                float add = -w * pind;
                atomicAdd(&g_Ap[nb], add);
                dC += (double)add * (double)pnb;
            }
            atomicAdd(&g_Ap[ind2], -acc2);
            dC -= (double)acc2 * (double)pind;
        }
        dC = bred(dC, sred);
        if (tid == 0) g_dotC[blockIdx.x] = dC;
        gbar(ep);

        // ---- Phase E: alpha; x,r update; rs_new partial
        {
            double v = 0.0;
            for (int i = tid; i < NBLK; i += TPB) v += g_dotA[i] + g_dotC[i];
            v = bred(v, sred);
            if (tid == 0) s_alpha = s_rs / v;
        }
        __syncthreads();
        float alpha = (float)s_alpha;
        double drs = 0.0;
        if (gtid < NPIX) {
            float pi = g_p[gtid];
            x[gtid] += alpha * pi;
            float rn = g_r[gtid] - alpha * g_Ap[gtid];
            g_r[gtid] = rn;
            drs = (double)rn * (double)rn;
        }
        drs = bred(drs, sred);
        if (tid == 0) g_rsn[blockIdx.x] = drs;
        gbar(ep);

        // ---- Phase F: beta; p update
        {
            double v = 0.0;
            for (int i = tid; i < NBLK; i += TPB) v += g_rsn[i];
            v = bred(v, sred);
            if (tid == 0) { s_beta = v / s_rs; s_rs = v; }
        }
        __syncthreads();
        float beta = (float)s_beta;
        if (gtid < NPIX) g_p[gtid] = g_r[gtid] + beta * g_p[gtid];
        gbar(ep);
    }
}

// ---------------- host launch ----------------
extern "C" void kernel_launch(void* const* d_in, const int* in_sizes, int n_in,
                              void* d_out, int out_size) {
    const float* CMw    = (const float*)d_in[0];
    const float* LOCw   = (const float*)d_in[1];
    const float* IUw    = (const float*)d_in[2];
    const float* KUw    = (const float*)d_in[3];
    const float* lmbda  = (const float*)d_in[4];
    const float* kToUcf = (const float*)d_in[5];
    const float* known  = (const float*)d_in[6];
    const float* kToU   = (const float*)d_in[7];
    const float* Wd     = (const float*)d_in[8];
    const float* LF     = (const float*)d_in[9];
    const float* IUf    = (const float*)d_in[10];
    const int*   wrow   = (const int*)d_in[11];
    const int*   wcol   = (const int*)d_in[12];
    const int*   locInd = (const int*)d_in[13];
    const int*   iuInd  = (const int*)d_in[14];
    const int*   iuNb   = (const int*)d_in[15];
    float* x = (float*)d_out;

    const int gN   = (NPIX + TPB - 1) / TPB;
    const int gNNZ = (NNZC + TPB - 1) / TPB;
    const int gP2  = (9 * NLOC + TPB - 1) / TPB;
    const int gL   = (NLOC + TPB - 1) / TPB;

    k_z<<<gN, TPB>>>();
    k_cnt<<<gNNZ, TPB>>>(CMw, Wd, wrow, wcol);
    k_scanA<<<288, 1024>>>();
    k_scanB<<<1, 32>>>();
    k_scanC<<<288, 1024>>>();
    k_scatter<<<gNNZ, TPB>>>(wrow, wcol);
    k_p2<<<gP2, TPB>>>(LOCw, LF, locInd);
    k_p3<<<gL, TPB>>>(IUw, IUf, iuInd, iuNb);
    k_p4<<<gN, TPB>>>(KUw, kToUcf, known, kToU, lmbda, x);
    k_cg<<<NBLK, TPB>>>(x, locInd, iuInd, iuNb);
}

// round 4
// speedup vs baseline: 1.6819x; 1.2259x over previous
#include <cuda_runtime.h>

// ---------------- problem constants (fixed by dataset) ----------------
#define NPIX 147456        // 384*384
#define W384 384
#define NNZC 1474560       // NPIX/2 * 20
#define NLOC 73728         // NPIX/2
#define KIU  5
#define CG_STEPS 30

#define TPB   512
#define NBLK  288          // 288*512 == NPIX exactly; 2 blocks/SM on 148 SMs
#define MPB   256          // matting pixels per block (NLOC / NBLK)

// ---------------- device scratch (static only) ----------------
__device__ int2  g_pairR[NNZC];        // CSR-sorted {col, val-bits}
__device__ int2  g_pairC[NNZC];        // CSC-sorted {row, val-bits}
__device__ float g_cm_vals[NNZC];
__device__ int   g_ptrR[NPIX + 1];
__device__ int   g_ptrC[NPIX + 1];
__device__ int   g_cntR[NPIX];
__device__ int   g_cntC[NPIX];
__device__ int   g_tmpR[NPIX];
__device__ int   g_tmpC[NPIX];
__device__ int   g_btot[288];
__device__ int   g_boff[288];

__device__ float g_rs_cm[NPIX];
__device__ float g_D[NPIX];
__device__ float g_S45[45 * NLOC];     // symmetric matting blocks [t*NLOC + k]
__device__ float g_Wiu[KIU * NLOC];    // [l*NLOC + k]
__device__ int   g_iuNbT[KIU * NLOC];  // transposed neighbor indices
__device__ float g_r[NPIX];
__device__ float g_p[NPIX];
__device__ float g_s[NPIX];
__device__ float g_w[NPIX];            // w = A r accumulator
__device__ float g_Lv[NPIX];
__device__ double g_dotG[NBLK];        // gamma partials
__device__ double g_dotD[NBLK];        // delta partials (phase A)
__device__ double g_dotD2[NBLK];       // delta partials (phase C)

__device__ unsigned g_count;
__device__ volatile unsigned g_sense;

// ---------------- helpers ----------------
__device__ __forceinline__ int OFF9(int i) {
    int a = i / 3, b = i % 3;
    return (a - 1) + (b - 1) * W384;
}
// triangular index for (i<=j) pair
__device__ __forceinline__ int TIDX(int i, int j) {
    return 9 * i - (i * (i - 1)) / 2 + (j - i);
}

__device__ __forceinline__ double bred(double v, double* sm) {
    int lane = threadIdx.x & 31, w = threadIdx.x >> 5;
    #pragma unroll
    for (int o = 16; o > 0; o >>= 1) v += __shfl_down_sync(0xffffffffu, v, o);
    if (lane == 0) sm[w] = v;
    __syncthreads();
    if (w == 0) {
        v = (lane < (TPB >> 5)) ? sm[lane] : 0.0;
        #pragma unroll
        for (int o = 8; o > 0; o >>= 1) v += __shfl_down_sync(0xffffu, v, o);
    }
    __syncthreads();
    return v; // valid on thread 0
}

__device__ __forceinline__ void gbar(unsigned &ep) {
    ep++;
    __syncthreads();
    if (threadIdx.x == 0) {
        __threadfence();
        if (atomicAdd(&g_count, 1u) == NBLK - 1) {
            g_count = 0;
            __threadfence();
            g_sense = ep;
        } else {
            while (g_sense != ep) { __nanosleep(32); }
            __threadfence();
        }
    }
    __syncthreads();
}

// ---------------- setup kernels ----------------
__global__ void k_z() {
    int i = blockIdx.x * blockDim.x + threadIdx.x;
    if (i < NPIX) {
        g_cntR[i] = 0; g_cntC[i] = 0; g_tmpR[i] = 0; g_tmpC[i] = 0;
        g_rs_cm[i] = 0.f; g_D[i] = 0.f;
    }
    if (i == 0) { g_count = 0; g_sense = 0; }
}

__global__ void k_cnt(const float* __restrict__ CMw, const float* __restrict__ Wd,
                      const int* __restrict__ row, const int* __restrict__ col) {
    int k = blockIdx.x * blockDim.x + threadIdx.x;
    if (k >= NNZC) return;
    int r = row[k], c = col[k];
    float cv = CMw[r] * Wd[k];
    g_cm_vals[k] = cv;
    atomicAdd(&g_rs_cm[r], cv);
    atomicAdd(&g_cntR[r], 1);
    atomicAdd(&g_cntC[c], 1);
}

// 288 blocks x 1024: blocks 0..143 scan cntR, 144..287 scan cntC (within-block)
__global__ void k_scanA() {
    __shared__ int sm[1024];
    int half = blockIdx.x / 144;
    int blk  = blockIdx.x % 144;
    int gi   = blk * 1024 + threadIdx.x;
    int* cnt = half ? g_cntC : g_cntR;
    int* ptr = half ? g_ptrC : g_ptrR;
    int v = cnt[gi];
    sm[threadIdx.x] = v;
    __syncthreads();
    for (int o = 1; o < 1024; o <<= 1) {
        int t = (threadIdx.x >= o) ? sm[threadIdx.x - o] : 0;
        __syncthreads();
        sm[threadIdx.x] += t;
        __syncthreads();
    }
    ptr[gi] = sm[threadIdx.x] - v;
    if (threadIdx.x == 1023) g_btot[blockIdx.x] = sm[1023];
}

// parallel block-offset scan (two independent halves of 144)
__global__ void k_scanB() {
    __shared__ int sm[288];
    int t = threadIdx.x;
    int v = (t < 288) ? g_btot[t] : 0;
    if (t < 288) sm[t] = v;
    __syncthreads();
    for (int o = 1; o < 288; o <<= 1) {
        int add = 0;
        if (t < 288 && t >= o) add = sm[t - o];
        __syncthreads();
        if (t < 288) sm[t] += add;
        __syncthreads();
    }
    if (t < 288) {
        int ex = sm[t] - v;                       // exclusive over all 288
        int base = (t >= 144) ? sm[143] : 0;      // total of first half
        g_boff[t] = ex - base;
    }
}

__global__ void k_scanC() {
    int half = blockIdx.x / 144;
    int blk  = blockIdx.x % 144;
    int gi   = blk * 1024 + threadIdx.x;
    int* ptr = half ? g_ptrC : g_ptrR;
    ptr[gi] += g_boff[blockIdx.x];
    if (blockIdx.x == 0 && threadIdx.x == 0) {
        g_ptrR[NPIX] = NNZC;
        g_ptrC[NPIX] = NNZC;
    }
}

__global__ void k_scatter(const int* __restrict__ row, const int* __restrict__ col) {
    int k = blockIdx.x * blockDim.x + threadIdx.x;
    if (k >= NNZC) return;
    int r = row[k], c = col[k];
    int vb = __float_as_int(g_cm_vals[k]);
    int p1 = g_ptrR[r] + atomicAdd(&g_tmpR[r], 1);
    g_pairR[p1] = make_int2(c, vb);
    int p2 = g_ptrC[c] + atomicAdd(&g_tmpC[c], 1);
    g_pairC[p2] = make_int2(r, vb);
}

// symmetric matting blocks: one thread per unknown pixel
__global__ void k_p2(const float* __restrict__ LOCw, const float* __restrict__ LF,
                     const int* __restrict__ inInd) {
    int m = blockIdx.x * blockDim.x + threadIdx.x;
    if (m >= NLOC) return;
    int ind = inInd[m];
    float w = LOCw[ind];
    float rs[9];
    #pragma unroll
    for (int i = 0; i < 9; i++) rs[i] = 0.f;
    #pragma unroll
    for (int i = 0; i < 9; i++) {
        #pragma unroll
        for (int j = i; j < 9; j++) {
            float s = 0.5f * w * (LF[(j * 9 + i) * NLOC + m] + LF[(i * 9 + j) * NLOC + m]);
            g_S45[TIDX(i, j) * NLOC + m] = s;
            rs[i] += s;
            if (j > i) rs[j] += s;
        }
    }
    #pragma unroll
    for (int i = 0; i < 9; i++) atomicAdd(&g_D[ind + OFF9(i)], rs[i]);
}

__global__ void k_p3(const float* __restrict__ IUw, const float* __restrict__ IUf,
                     const int* __restrict__ inInd, const int* __restrict__ nbInd) {
    int k = blockIdx.x * blockDim.x + threadIdx.x;
    if (k >= NLOC) return;
    int ind = inInd[k];
    float w = IUw[ind];
    #pragma unroll
    for (int l = 0; l < KIU; l++) {
        float wv = 0.5f * w * IUf[k * KIU + l];
        int nb = nbInd[k * KIU + l];
        g_Wiu[l * NLOC + k] = wv;
        g_iuNbT[l * NLOC + k] = nb;
        atomicAdd(&g_D[ind], wv);
        atomicAdd(&g_D[nb], wv);
    }
}

__global__ void k_p4(const float* __restrict__ KUw, const float* __restrict__ kToUconf,
                     const float* __restrict__ known, const float* __restrict__ kToU,
                     const float* __restrict__ lmbda, float* __restrict__ x) {
    int i = blockIdx.x * blockDim.x + threadIdx.x;
    if (i >= NPIX) return;
    float dk = KUw[i] * kToUconf[i] + lmbda[0] * known[i];
    float b  = dk * kToU[i];
    g_D[i] += dk;
    g_r[i] = b;     // r0 = b (x0 = 0)
    x[i] = 0.f;
}

// ---------------- persistent single-reduction CG kernel ----------------
__global__ void __launch_bounds__(TPB, 2) k_cg(
    float* __restrict__ x,
    const int* __restrict__ locInd,
    const int* __restrict__ iuInd)
{
    __shared__ double sred[16];
    __shared__ double s_g;                 // dedicated slot for reduced gamma
    __shared__ double s_alpha, s_beta, s_gamma_prev, s_alpha_prev;
    const int tid  = threadIdx.x;
    const int gtid = blockIdx.x * TPB + tid;     // always < NPIX
    const int m    = blockIdx.x * MPB + tid;     // matting pixel if tid < MPB
    unsigned ep = 0;

    for (int it = 0; it < CG_STEPS; ++it) {
        // ---- Phase A: w_init = Lcm-diag part + D; gamma & delta partials
        float ri;
        {
            int b0 = g_ptrR[gtid], b1 = g_ptrR[gtid + 1];
            float acc = 0.f;
            int k = b0;
            for (; k + 4 <= b1; k += 4) {
                int2 e0 = g_pairR[k],     e1 = g_pairR[k + 1];
                int2 e2 = g_pairR[k + 2], e3 = g_pairR[k + 3];
                acc += __int_as_float(e0.y) * g_r[e0.x]
                     + __int_as_float(e1.y) * g_r[e1.x]
                     + __int_as_float(e2.y) * g_r[e2.x]
                     + __int_as_float(e3.y) * g_r[e3.x];
            }
            for (; k < b1; k++) {
                int2 e = g_pairR[k];
                acc += __int_as_float(e.y) * g_r[e.x];
            }
            ri = g_r[gtid];
            float rc = g_rs_cm[gtid];
            float lv = rc * ri - acc;
            g_Lv[gtid] = lv;
            float wi = rc * lv + g_D[gtid] * ri;
            g_w[gtid] = wi;
            double dG = (double)ri * (double)ri;
            double dD = (double)ri * (double)wi;
            dG = bred(dG, sred);
            if (tid == 0) g_dotG[blockIdx.x] = dG;
            dD = bred(dD, sred);
            if (tid == 0) g_dotD[blockIdx.x] = dD;
        }
        gbar(ep);

        // ---- Phase C: off-diagonal scatters + fused delta contributions
        {
            double dD = 0.0;
            // CSC: w[i] -= sum vals_c * Lv[row]
            {
                int b0 = g_ptrC[gtid], b1 = g_ptrC[gtid + 1];
                float acc = 0.f;
                int k = b0;
                for (; k + 4 <= b1; k += 4) {
                    int2 e0 = g_pairC[k],     e1 = g_pairC[k + 1];
                    int2 e2 = g_pairC[k + 2], e3 = g_pairC[k + 3];
                    acc += __int_as_float(e0.y) * g_Lv[e0.x]
                         + __int_as_float(e1.y) * g_Lv[e1.x]
                         + __int_as_float(e2.y) * g_Lv[e2.x]
                         + __int_as_float(e3.y) * g_Lv[e3.x];
                }
                for (; k < b1; k++) {
                    int2 e = g_pairC[k];
                    acc += __int_as_float(e.y) * g_Lv[e.x];
                }
                atomicAdd(&g_w[gtid], -acc);
                dD -= (double)acc * (double)ri;
            }
            if (tid < MPB) {
                // symmetric 9x9 matting block
                int ind = locInd[m];
                float pn[9], acc9[9];
                #pragma unroll
                for (int j = 0; j < 9; j++) { pn[j] = g_r[ind + OFF9(j)]; acc9[j] = 0.f; }
                #pragma unroll
                for (int i9 = 0; i9 < 9; i9++) {
                    #pragma unroll
                    for (int j9 = i9; j9 < 9; j9++) {
                        float v = g_S45[TIDX(i9, j9) * NLOC + m];
                        acc9[i9] += v * pn[j9];
                        if (j9 > i9) acc9[j9] += v * pn[i9];
                    }
                }
                #pragma unroll
                for (int i9 = 0; i9 < 9; i9++) {
                    atomicAdd(&g_w[ind + OFF9(i9)], -acc9[i9]);
                    dD -= (double)acc9[i9] * (double)pn[i9];
                }
                // IU KNN
                int ind2 = iuInd[m];
                float rind = g_r[ind2];
                float acc2 = 0.f;
                #pragma unroll
                for (int l = 0; l < KIU; l++) {
                    float wv = g_Wiu[l * NLOC + m];
                    int nb   = g_iuNbT[l * NLOC + m];
                    float rnb = g_r[nb];
                    acc2 += wv * rnb;
                    atomicAdd(&g_w[nb], -wv * rind);
                    dD -= (double)(wv * rind) * (double)rnb;
                }
                atomicAdd(&g_w[ind2], -acc2);
                dD -= (double)acc2 * (double)rind;
            }
            dD = bred(dD, sred);
            if (tid == 0) g_dotD2[blockIdx.x] = dD;
        }
        gbar(ep);

        // ---- Phase U: reduce gamma/delta; alpha,beta; fused p,s,x,r update
        {
            double gamma = 0.0, delta = 0.0;
            if (tid < NBLK) {
                gamma = g_dotG[tid];
                delta = g_dotD[tid] + g_dotD2[tid];
            }
            gamma = bred(gamma, sred);
            if (tid == 0) s_g = gamma;          // dedicated slot, no alias with sred
            delta = bred(delta, sred);
            if (tid == 0) {
                gamma = s_g;
                double beta, alpha;
                if (it == 0) {
                    beta = 0.0;
                    alpha = gamma / delta;
                } else {
                    beta = gamma / s_gamma_prev;
                    alpha = gamma / (delta - beta * gamma / s_alpha_prev);
                }
                s_alpha = alpha; s_beta = beta;
                s_gamma_prev = gamma; s_alpha_prev = alpha;
            }
            __syncthreads();
            float alpha = (float)s_alpha;
            float beta  = (float)s_beta;
            float wi = g_w[gtid];
            float pi, si;
            if (it == 0) { pi = ri; si = wi; }
            else {
                pi = ri + beta * g_p[gtid];
                si = wi + beta * g_s[gtid];
            }
            g_p[gtid] = pi;
            g_s[gtid] = si;
            x[gtid] += alpha * pi;
            g_r[gtid] = ri - alpha * si;
        }
        if (it + 1 < CG_STEPS) gbar(ep);
    }
}

// ---------------- host launch ----------------
extern "C" void kernel_launch(void* const* d_in, const int* in_sizes, int n_in,
                              void* d_out, int out_size) {
    const float* CMw    = (const float*)d_in[0];
    const float* LOCw   = (const float*)d_in[1];
    const float* IUw    = (const float*)d_in[2];
    const float* KUw    = (const float*)d_in[3];
    const float* lmbda  = (const float*)d_in[4];
    const float* kToUcf = (const float*)d_in[5];
    const float* known  = (const float*)d_in[6];
    const float* kToU   = (const float*)d_in[7];
    const float* Wd     = (const float*)d_in[8];
    const float* LF     = (const float*)d_in[9];
    const float* IUf    = (const float*)d_in[10];
    const int*   wrow   = (const int*)d_in[11];
    const int*   wcol   = (const int*)d_in[12];
    const int*   locInd = (const int*)d_in[13];
    const int*   iuInd  = (const int*)d_in[14];
    const int*   iuNb   = (const int*)d_in[15];
    float* x = (float*)d_out;

    const int gN   = (NPIX + 255) / 256;
    const int gNNZ = (NNZC + 255) / 256;
    const int gL   = (NLOC + 255) / 256;

    k_z<<<gN, 256>>>();
    k_cnt<<<gNNZ, 256>>>(CMw, Wd, wrow, wcol);
    k_scanA<<<288, 1024>>>();
    k_scanB<<<1, 320>>>();
    k_scanC<<<288, 1024>>>();
    k_scatter<<<gNNZ, 256>>>(wrow, wcol);
    k_p2<<<gL, 256>>>(LOCw, LF, locInd);
    k_p3<<<gL, 256>>>(IUw, IUf, iuInd, iuNb);
    k_p4<<<gN, 256>>>(KUw, kToUcf, known, kToU, lmbda, x);
    k_cg<<<NBLK, TPB>>>(x, locInd, iuInd);
}